// round 10
// baseline (speedup 1.0000x reference)
#include <cuda_runtime.h>
#include <cuda_fp16.h>

// Problem constants: N = 1<<20 per row, B*C = 4 rows.
#define N_ROW   (1 << 20)
#define TABLE_N 256
#define XMIN    (-10.0f)
#define XSPAN   (20.0f)
#define HSTEP   (XSPAN / (float)TABLE_N)

#define GRID_MAIN  1184        // 148 SMs x 8 resident blocks: one persistent wave
#define BLOCK_MAIN 256
#define CHUNK      8           // floats per thread per chunk
#define STRIDE     (GRID_MAIN * BLOCK_MAIN * CHUNK)   // 2,424,832 floats

// Tabulated correction f(x) at TABLE_N+1 points over [XMIN, XMIN+XSPAN].
__device__ float        g_f[TABLE_N + 1];
__device__ unsigned int g_done;   // table points published (0 at load; reset each call)
__device__ unsigned int g_fin;    // blocks finished (for the reset)

// ---------------------------------------------------------------------------
// Per-chunk compute: 8 consecutive floats already loaded in (a,b,edge).
// ---------------------------------------------------------------------------
__device__ __forceinline__ void compute_store_chunk(float* __restrict__ out,
                                                    int i, int lane,
                                                    float4 a, float4 b, float edge,
                                                    const unsigned int* tab) {
    float left  = __shfl_up_sync(0xffffffffu, b.w, 1);
    float right = __shfl_down_sync(0xffffffffu, a.x, 1);
    if (lane == 0)  left  = edge;
    if (lane == 31) right = edge;

    float v[10];
    v[0] = left;
    v[1] = a.x; v[2] = a.y; v[3] = a.z; v[4] = a.w;
    v[5] = b.x; v[6] = b.y; v[7] = b.z; v[8] = b.w;
    v[9] = right;

    float r[8];
#pragma unroll
    for (int j = 0; j < 8; ++j) {
        float lap = fmaf(-2.0f, v[j + 1], v[j] + v[j + 2]);
        float tn  = __saturatef(fmaf(v[j + 1], 1.0f / XSPAN, 0.5f));
        float tf  = tn * ((float)TABLE_N - 0.004f);
        int   ki  = (int)tf;
        float fr  = tf - (float)ki;
        unsigned int pk = tab[ki];
        __half2 h2 = *reinterpret_cast<const __half2*>(&pk);
        float2 e = __half22float2(h2);
        r[j] = lap + fmaf(e.y - e.x, fr, e.x);
    }

    __stcs(reinterpret_cast<float4*>(out + i),
           make_float4(r[0], r[1], r[2], r[3]));
    __stcs(reinterpret_cast<float4*>(out + i + 4),
           make_float4(r[4], r[5], r[6], r[7]));
}

__device__ __forceinline__ float load_edge(const float* __restrict__ u,
                                           int i, int lane) {
    float edge = 0.0f;
    if (lane == 0 && (i & (N_ROW - 1)) != 0)
        edge = __ldg(u + i - 1);
    if (lane == 31 && ((i + CHUNK) & (N_ROW - 1)) != 0)
        edge = __ldg(u + i + CHUNK);
    return edge;
}

// ---------------------------------------------------------------------------
// Fused kernel: persistent single wave (1184 blocks x 256 threads).
//   Blocks 0..TABLE_N: warp 0 computes one exact-MLP table point -> g_f.
//   All blocks: issue chunk-A LDGs first, spin on g_done (overlapped with
//   the DRAM latency), fill the 1KB half2 smem table, then compute chunks.
//   Last block resets the counters so graph replays are deterministic.
// ---------------------------------------------------------------------------
__global__ __launch_bounds__(BLOCK_MAIN, 8) void lap_corr_fused_kernel(
        const float* __restrict__ u, float* __restrict__ out,
        const float* __restrict__ W1, const float* __restrict__ b1,
        const float* __restrict__ W2, const float* __restrict__ b2,
        const float* __restrict__ W3, const float* __restrict__ b3,
        int total) {
    __shared__ unsigned int tab[TABLE_N];

    const int tid  = threadIdx.x;
    const int t    = blockIdx.x * BLOCK_MAIN + tid;
    const int i0   = t * CHUNK;                  // chunk A (< STRIDE <= total here)
    const int lane = tid & 31;
    const int wid  = tid >> 5;
    const bool liveA = (i0 < total);

    // ---- chunk A loads first: DRAM latency overlaps the table handshake ----
    float4 a0 = make_float4(0.f, 0.f, 0.f, 0.f);
    float4 b0 = make_float4(0.f, 0.f, 0.f, 0.f);
    float  e0 = 0.0f;
    if (liveA) {
        a0 = *reinterpret_cast<const float4*>(u + i0);
        b0 = *reinterpret_cast<const float4*>(u + i0 + 4);
        e0 = load_edge(u, i0, lane);
    }

    // ---- producer: blocks 0..TABLE_N, warp 0 computes one table point ----
    if (blockIdx.x <= TABLE_N && wid == 0) {
        float x   = XMIN + (float)blockIdx.x * HSTEP;
        float h1  = tanhf(fmaf(__ldg(W1 + lane), x, __ldg(b1 + lane)));
        float acc = __ldg(b2 + lane);
#pragma unroll
        for (int k = 0; k < 32; ++k) {
            float hk = __shfl_sync(0xffffffffu, h1, k);
            acc = fmaf(hk, __ldg(W2 + k * 32 + lane), acc);
        }
        float p = tanhf(acc) * __ldg(W3 + lane);
#pragma unroll
        for (int off = 16; off > 0; off >>= 1)
            p += __shfl_xor_sync(0xffffffffu, p, off);
        if (lane == 0) {
            g_f[blockIdx.x] = p + __ldg(b3);
            __threadfence();                     // publish g_f before counting
            atomicAdd(&g_done, 1u);
        }
    }

    // ---- consumer handshake: thread 0 spins, rest wait at the barrier ----
    if (tid == 0) {
        volatile unsigned int* p = &g_done;
        while (*p < (unsigned)(TABLE_N + 1)) { }
        __threadfence();                         // acquire: order g_f reads
    }
    __syncthreads();

    // ---- smem table fill: one half2 entry per thread ----
    {
        float v0 = g_f[tid];
        float v1 = __shfl_down_sync(0xffffffffu, v0, 1);
        if (lane == 31) v1 = g_f[tid + 1];       // g_f[256] valid at tid=255
        __half2 h = __float22half2_rn(make_float2(v0, v1));
        tab[tid] = *reinterpret_cast<unsigned int*>(&h);
    }
    __syncthreads();

    // ---- main work ----
    if (liveA)
        compute_store_chunk(out, i0, lane, a0, b0, e0, tab);

    const int i1 = i0 + STRIDE;
    if (i1 < total) {
        float4 a1 = *reinterpret_cast<const float4*>(u + i1);
        float4 b1v = *reinterpret_cast<const float4*>(u + i1 + 4);
        float  e1 = load_edge(u, i1, lane);
        compute_store_chunk(out, i1, lane, a1, b1v, e1, tab);
    }

    // ---- reset counters for the next graph replay ----
    if (tid == 0) {
        __threadfence();
        if (atomicAdd(&g_fin, 1u) == (unsigned)(GRID_MAIN - 1)) {
            g_done = 0u;
            g_fin  = 0u;
        }
    }
}

// ---------------------------------------------------------------------------
// Launch: a single graph node.
// ---------------------------------------------------------------------------
extern "C" void kernel_launch(void* const* d_in, const int* in_sizes, int n_in,
                              void* d_out, int out_size) {
    const float* u  = (const float*)d_in[0];
    const float* W1 = (const float*)d_in[1];
    const float* b1 = (const float*)d_in[2];
    const float* W2 = (const float*)d_in[3];
    const float* b2 = (const float*)d_in[4];
    const float* W3 = (const float*)d_in[5];
    const float* b3 = (const float*)d_in[6];
    float* out = (float*)d_out;
    const int total = in_sizes[0];               // 4 * 1048576

    lap_corr_fused_kernel<<<GRID_MAIN, BLOCK_MAIN>>>(u, out, W1, b1, W2, b2,
                                                     W3, b3, total);
}

// round 13
// speedup vs baseline: 1.3208x; 1.3208x over previous
#include <cuda_runtime.h>

// Problem constants: N = 1<<20 per row, B*C = 4 rows.
#define N_ROW   (1 << 20)
#define TABLE_N 256
#define XMIN    (-10.0f)
#define XSPAN   (20.0f)
#define HSTEP   (XSPAN / (float)TABLE_N)

#define GRID_MAIN  1184        // 148 SMs x 8 resident blocks: one persistent wave
#define BLOCK_MAIN 256
#define CHUNK      8           // floats per thread per chunk
#define STRIDE     (GRID_MAIN * BLOCK_MAIN * CHUNK)   // 2,424,832 floats

// Tabulated correction f(x) at TABLE_N+1 points over [XMIN, XMIN+XSPAN].
__device__ float g_f[TABLE_N + 1];

// ---------------------------------------------------------------------------
// Kernel 1: build the correction table (exact MLP). One warp per table point.
// Fires its PDL completion trigger as soon as every block has published.
// ---------------------------------------------------------------------------
__global__ void build_table_kernel(const float* __restrict__ W1,
                                   const float* __restrict__ b1,
                                   const float* __restrict__ W2,
                                   const float* __restrict__ b2,
                                   const float* __restrict__ W3,
                                   const float* __restrict__ b3) {
    int warp = (blockIdx.x * blockDim.x + threadIdx.x) >> 5;
    int lane = threadIdx.x & 31;
    if (warp <= TABLE_N) {
        float x  = XMIN + (float)warp * HSTEP;
        float h1 = tanhf(fmaf(__ldg(W1 + lane), x, __ldg(b1 + lane)));
        float acc = __ldg(b2 + lane);
#pragma unroll
        for (int k = 0; k < 32; ++k) {
            float hk = __shfl_sync(0xffffffffu, h1, k);
            acc = fmaf(hk, __ldg(W2 + k * 32 + lane), acc);
        }
        float p = tanhf(acc) * __ldg(W3 + lane);
#pragma unroll
        for (int off = 16; off > 0; off >>= 1)
            p += __shfl_xor_sync(0xffffffffu, p, off);
        if (lane == 0) g_f[warp] = p + __ldg(b3);
    }
    __syncthreads();
    cudaTriggerProgrammaticLaunchCompletion();   // release dependent grid early
}

// ---------------------------------------------------------------------------
// Per-chunk compute: 8 consecutive floats already loaded in (a,b,edge).
// Table entries are {f_k, f_{k+1}-f_k} -> lerp is one FMA.
// ---------------------------------------------------------------------------
__device__ __forceinline__ void compute_store_chunk(float* __restrict__ out,
                                                    int i, int lane,
                                                    float4 a, float4 b, float edge,
                                                    const float2* tab) {
    float left  = __shfl_up_sync(0xffffffffu, b.w, 1);
    float right = __shfl_down_sync(0xffffffffu, a.x, 1);
    if (lane == 0)  left  = edge;
    if (lane == 31) right = edge;

    float v[10];
    v[0] = left;
    v[1] = a.x; v[2] = a.y; v[3] = a.z; v[4] = a.w;
    v[5] = b.x; v[6] = b.y; v[7] = b.z; v[8] = b.w;
    v[9] = right;

    float r[8];
#pragma unroll
    for (int j = 0; j < 8; ++j) {
        float lap = fmaf(-2.0f, v[j + 1], v[j] + v[j + 2]);
        float tn  = __saturatef(fmaf(v[j + 1], 1.0f / XSPAN, 0.5f));
        float tf  = tn * ((float)TABLE_N - 0.004f);
        int   ki  = (int)tf;
        float fr  = tf - (float)ki;
        float2 e  = tab[ki];
        r[j] = lap + fmaf(fr, e.y, e.x);
    }

    __stcs(reinterpret_cast<float4*>(out + i),
           make_float4(r[0], r[1], r[2], r[3]));
    __stcs(reinterpret_cast<float4*>(out + i + 4),
           make_float4(r[4], r[5], r[6], r[7]));
}

__device__ __forceinline__ float load_edge(const float* __restrict__ u,
                                           int i, int lane) {
    float edge = 0.0f;
    if (lane == 0 && (i & (N_ROW - 1)) != 0)
        edge = __ldg(u + i - 1);
    if (lane == 31 && ((i + CHUNK) & (N_ROW - 1)) != 0)
        edge = __ldg(u + i + CHUNK);
    return edge;
}

// ---------------------------------------------------------------------------
// Kernel 2 (PDL secondary): persistent single wave, 1184 x 256.
//   Prologue: issue chunk-A LDGs BEFORE cudaGridDependencySynchronize() so
//   the DRAM latency overlaps the tail of the build kernel + dependency wait.
// ---------------------------------------------------------------------------
__global__ __launch_bounds__(BLOCK_MAIN, 8) void lap_corr_kernel(
        const float* __restrict__ u, float* __restrict__ out, int total) {
    __shared__ float2 tab[TABLE_N];

    const int tid  = threadIdx.x;
    const int t    = blockIdx.x * BLOCK_MAIN + tid;
    const int i0   = t * CHUNK;                  // always < STRIDE <= total
    const int lane = tid & 31;

    // ---- chunk A loads first: independent of g_f ----
    float4 a0 = *reinterpret_cast<const float4*>(u + i0);
    float4 b0 = *reinterpret_cast<const float4*>(u + i0 + 4);
    float  e0 = load_edge(u, i0, lane);

    // ---- wait for the build kernel's writes to be visible ----
    cudaGridDependencySynchronize();

    // ---- smem table fill: one {f, df} entry per thread ----
    {
        float v0 = g_f[tid];
        float v1 = __shfl_down_sync(0xffffffffu, v0, 1);
        if (lane == 31) v1 = g_f[tid + 1];       // g_f[256] valid at tid=255
        tab[tid] = make_float2(v0, v1 - v0);
    }
    __syncthreads();

    compute_store_chunk(out, i0, lane, a0, b0, e0, tab);

    const int i1 = i0 + STRIDE;
    if (i1 < total) {
        float4 a1 = *reinterpret_cast<const float4*>(u + i1);
        float4 b1 = *reinterpret_cast<const float4*>(u + i1 + 4);
        float  e1 = load_edge(u, i1, lane);
        compute_store_chunk(out, i1, lane, a1, b1, e1, tab);
    }
}

// ---------------------------------------------------------------------------
// Launch: build kernel, then PDL-overlapped main kernel.
// ---------------------------------------------------------------------------
extern "C" void kernel_launch(void* const* d_in, const int* in_sizes, int n_in,
                              void* d_out, int out_size) {
    const float* u  = (const float*)d_in[0];
    const float* W1 = (const float*)d_in[1];
    const float* b1 = (const float*)d_in[2];
    const float* W2 = (const float*)d_in[3];
    const float* b2 = (const float*)d_in[4];
    const float* W3 = (const float*)d_in[5];
    const float* b3 = (const float*)d_in[6];
    float* out = (float*)d_out;
    const int total = in_sizes[0];               // 4 * 1048576

    build_table_kernel<<<(TABLE_N + 1 + 7) / 8, 256>>>(W1, b1, W2, b2, W3, b3);

    cudaLaunchConfig_t cfg = {};
    cfg.gridDim  = dim3(GRID_MAIN, 1, 1);
    cfg.blockDim = dim3(BLOCK_MAIN, 1, 1);
    cfg.dynamicSmemBytes = 0;
    cfg.stream = 0;
    cudaLaunchAttribute attr;
    attr.id = cudaLaunchAttributeProgrammaticStreamSerialization;
    attr.val.programmaticStreamSerializationAllowed = 1;
    cfg.attrs = &attr;
    cfg.numAttrs = 1;
    cudaLaunchKernelEx(&cfg, lap_corr_kernel, u, out, total);
}

// round 15
// speedup vs baseline: 1.3241x; 1.0025x over previous
#include <cuda_runtime.h>

// Problem constants: N = 1<<20 per row, B*C = 4 rows.
#define N_ROW   (1 << 20)
#define TABLE_N 256
#define XMIN    (-10.0f)
#define XSPAN   (20.0f)
#define HSTEP   (XSPAN / (float)TABLE_N)

#define GRID_MAIN  1184
#define BLOCK_MAIN 256
#define CHUNK      8
#define STRIDE     (GRID_MAIN * BLOCK_MAIN * CHUNK)   // 2,424,832 floats

// Tabulated correction f(x) at TABLE_N+1 points over [XMIN, XMIN+XSPAN].
__device__ float g_f[TABLE_N + 1];

// ---------------------------------------------------------------------------
// Kernel 1: build the correction table (exact MLP). One warp per table point.
// ---------------------------------------------------------------------------
__global__ void build_table_kernel(const float* __restrict__ W1,
                                   const float* __restrict__ b1,
                                   const float* __restrict__ W2,
                                   const float* __restrict__ b2,
                                   const float* __restrict__ W3,
                                   const float* __restrict__ b3) {
    int warp = (blockIdx.x * blockDim.x + threadIdx.x) >> 5;
    int lane = threadIdx.x & 31;
    if (warp <= TABLE_N) {
        float x  = XMIN + (float)warp * HSTEP;
        float h1 = tanhf(fmaf(__ldg(W1 + lane), x, __ldg(b1 + lane)));
        float acc = __ldg(b2 + lane);
#pragma unroll
        for (int k = 0; k < 32; ++k) {
            float hk = __shfl_sync(0xffffffffu, h1, k);
            acc = fmaf(hk, __ldg(W2 + k * 32 + lane), acc);
        }
        float p = tanhf(acc) * __ldg(W3 + lane);
#pragma unroll
        for (int off = 16; off > 0; off >>= 1)
            p += __shfl_xor_sync(0xffffffffu, p, off);
        if (lane == 0) g_f[warp] = p + __ldg(b3);
    }
    __syncthreads();
    cudaTriggerProgrammaticLaunchCompletion();   // release dependent grid early
}

// ---------------------------------------------------------------------------
// Per-chunk compute: 8 consecutive floats already in (a,b,edge).
// Table entries {f_k, f_{k+1}-f_k} -> lerp is one FMA.
// ---------------------------------------------------------------------------
__device__ __forceinline__ void compute_store_chunk(float* __restrict__ out,
                                                    int i, int lane,
                                                    float4 a, float4 b, float edge,
                                                    const float2* tab) {
    float left  = __shfl_up_sync(0xffffffffu, b.w, 1);
    float right = __shfl_down_sync(0xffffffffu, a.x, 1);
    if (lane == 0)  left  = edge;
    if (lane == 31) right = edge;

    float v[10];
    v[0] = left;
    v[1] = a.x; v[2] = a.y; v[3] = a.z; v[4] = a.w;
    v[5] = b.x; v[6] = b.y; v[7] = b.z; v[8] = b.w;
    v[9] = right;

    float r[8];
#pragma unroll
    for (int j = 0; j < 8; ++j) {
        float lap = fmaf(-2.0f, v[j + 1], v[j] + v[j + 2]);
        float tn  = __saturatef(fmaf(v[j + 1], 1.0f / XSPAN, 0.5f));
        float tf  = tn * ((float)TABLE_N - 0.004f);
        int   ki  = (int)tf;
        float fr  = tf - (float)ki;
        float2 e  = tab[ki];
        r[j] = lap + fmaf(fr, e.y, e.x);
    }

    __stcs(reinterpret_cast<float4*>(out + i),
           make_float4(r[0], r[1], r[2], r[3]));
    __stcs(reinterpret_cast<float4*>(out + i + 4),
           make_float4(r[4], r[5], r[6], r[7]));
}

__device__ __forceinline__ float load_edge(const float* __restrict__ u,
                                           int i, int lane) {
    float edge = 0.0f;
    if (lane == 0 && (i & (N_ROW - 1)) != 0)
        edge = __ldg(u + i - 1);
    if (lane == 31 && ((i + CHUNK) & (N_ROW - 1)) != 0)
        edge = __ldg(u + i + CHUNK);
    return edge;
}

// ---------------------------------------------------------------------------
// Kernel 2 (PDL secondary): 1184 x 256, two strided chunks per thread.
//   ALL global loads (both chunks + halos) are issued before the PDL wait,
//   so each warp pays the DRAM latency once, overlapped with the build
//   kernel's tail, the dependency wait, the table fill, and chunk-A compute.
// ---------------------------------------------------------------------------
__global__ __launch_bounds__(BLOCK_MAIN, 6) void lap_corr_kernel(
        const float* __restrict__ u, float* __restrict__ out, int total) {
    __shared__ float2 tab[TABLE_N];

    const int tid  = threadIdx.x;
    const int t    = blockIdx.x * BLOCK_MAIN + tid;
    const int i0   = t * CHUNK;                  // always < STRIDE <= total
    const int i1   = i0 + STRIDE;
    const int lane = tid & 31;
    const bool liveB = (i1 < total);

    // ---- issue ALL independent loads up front (MLP_p1 = 6) ----
    float4 a0 = *reinterpret_cast<const float4*>(u + i0);
    float4 b0 = *reinterpret_cast<const float4*>(u + i0 + 4);
    float  e0 = load_edge(u, i0, lane);
    float4 a1 = make_float4(0.f, 0.f, 0.f, 0.f);
    float4 b1 = make_float4(0.f, 0.f, 0.f, 0.f);
    float  e1 = 0.0f;
    if (liveB) {
        a1 = *reinterpret_cast<const float4*>(u + i1);
        b1 = *reinterpret_cast<const float4*>(u + i1 + 4);
        e1 = load_edge(u, i1, lane);
    }

    // ---- wait for the build kernel's writes to be visible ----
    cudaGridDependencySynchronize();

    // ---- smem table fill: one {f, df} entry per thread ----
    {
        float v0 = g_f[tid];
        float v1 = __shfl_down_sync(0xffffffffu, v0, 1);
        if (lane == 31) v1 = g_f[tid + 1];       // g_f[256] valid at tid=255
        tab[tid] = make_float2(v0, v1 - v0);
    }
    __syncthreads();

    compute_store_chunk(out, i0, lane, a0, b0, e0, tab);
    if (liveB)
        compute_store_chunk(out, i1, lane, a1, b1, e1, tab);
}

// ---------------------------------------------------------------------------
// Launch: build kernel, then PDL-overlapped main kernel.
// ---------------------------------------------------------------------------
extern "C" void kernel_launch(void* const* d_in, const int* in_sizes, int n_in,
                              void* d_out, int out_size) {
    const float* u  = (const float*)d_in[0];
    const float* W1 = (const float*)d_in[1];
    const float* b1 = (const float*)d_in[2];
    const float* W2 = (const float*)d_in[3];
    const float* b2 = (const float*)d_in[4];
    const float* W3 = (const float*)d_in[5];
    const float* b3 = (const float*)d_in[6];
    float* out = (float*)d_out;
    const int total = in_sizes[0];               // 4 * 1048576

    build_table_kernel<<<(TABLE_N + 1 + 7) / 8, 256>>>(W1, b1, W2, b2, W3, b3);

    cudaLaunchConfig_t cfg = {};
    cfg.gridDim  = dim3(GRID_MAIN, 1, 1);
    cfg.blockDim = dim3(BLOCK_MAIN, 1, 1);
    cfg.dynamicSmemBytes = 0;
    cfg.stream = 0;
    cudaLaunchAttribute attr;
    attr.id = cudaLaunchAttributeProgrammaticStreamSerialization;
    attr.val.programmaticStreamSerializationAllowed = 1;
    cfg.attrs = &attr;
    cfg.numAttrs = 1;
    cudaLaunchKernelEx(&cfg, lap_corr_kernel, u, out, total);
}